// round 2
// baseline (speedup 1.0000x reference)
#include <cuda_runtime.h>
#include <cuda_bf16.h>
#include <math.h>

// Shapes (fixed by the problem)
#define B 128
#define T 2048
#define H 200
#define G4 800          // 4*H
#define NSTEP 5

// ---- scratch (device globals; no allocation allowed) ----
__device__ float g_qproj[B * H];     // q @ Wa.T + ba
__device__ float g_hpre [B * G4];    // q @ W_hh.T + b_hh
__device__ float g_scores[B * T];
__device__ float g_context[B * H];

__device__ __forceinline__ float sigm(float v) { return 1.0f / (1.0f + expf(-v)); }

// ============================================================
// Kernel 1: q_proj and h_pre (tiny)
// grid = B, block = 256
// ============================================================
__global__ void k_pre(const float* __restrict__ h0, const float* __restrict__ Wa,
                      const float* __restrict__ ba, const float* __restrict__ Whh,
                      const float* __restrict__ bhh) {
    __shared__ float q[H];
    const int b = blockIdx.x;
    for (int k = threadIdx.x; k < H; k += blockDim.x) q[k] = h0[b * H + k];
    __syncthreads();

    for (int j = threadIdx.x; j < H; j += blockDim.x) {
        const float* w = Wa + j * H;
        float a0 = 0.f, a1 = 0.f;
        #pragma unroll 4
        for (int k = 0; k < H; k += 2) { a0 += w[k] * q[k]; a1 += w[k + 1] * q[k + 1]; }
        g_qproj[b * H + j] = a0 + a1 + ba[j];
    }
    for (int j = threadIdx.x; j < G4; j += blockDim.x) {
        const float* w = Whh + j * H;
        float a0 = 0.f, a1 = 0.f;
        #pragma unroll 4
        for (int k = 0; k < H; k += 2) { a0 += w[k] * q[k]; a1 += w[k + 1] * q[k + 1]; }
        g_hpre[b * G4 + j] = a0 + a1 + bhh[j];
    }
}

// ============================================================
// Kernel 2: scores[b,t] = sum_n Va[n]*tanh(qproj[b,n]+bua[n] + sum_k enc[b,t,k]*Ua[n,k])
// The dominant GEMM, fused with tanh + Va reduction (k_proj never hits HBM).
// Block: 64 t-rows x full N=200.  320 threads, 8x5 register tile.
// ============================================================
#define TM 64
#define KC 40
#define NTH 320

__global__ __launch_bounds__(NTH, 2)
void k_scores(const float* __restrict__ enc, const float* __restrict__ Ua,
              const float* __restrict__ bua, const float* __restrict__ Va) {
    __shared__ float sE[TM][KC + 1];     // enc tile, padded (41 floats/row)
    __shared__ float sU[H][KC + 1];      // Ua tile, padded
    __shared__ float sQ[H];              // qproj + bua
    __shared__ float sV[H];
    __shared__ float sS[TM];

    const int b   = blockIdx.y;
    const int t0  = blockIdx.x * TM;
    const int tid = threadIdx.x;

    for (int i = tid; i < H; i += NTH) { sQ[i] = g_qproj[b * H + i] + bua[i]; sV[i] = Va[i]; }
    for (int i = tid; i < TM; i += NTH) sS[i] = 0.f;

    const int mg = tid / 40;       // 0..7  -> m0 = mg*8
    const int ng = tid % 40;       // 0..39 -> n0 = ng*5
    const int m0 = mg * 8;
    const int n0 = ng * 5;

    float acc[8][5];
    #pragma unroll
    for (int m = 0; m < 8; ++m)
        #pragma unroll
        for (int n = 0; n < 5; ++n) acc[m][n] = 0.f;

    const float* encB = enc + ((long)b * T + t0) * H;

    for (int kb = 0; kb < H; kb += KC) {
        __syncthreads();
        // load enc tile: rows of 40 contiguous floats -> coalesced
        for (int i = tid; i < TM * KC; i += NTH) {
            int m = i / KC, k = i - m * KC;
            sE[m][k] = encB[m * H + kb + k];
        }
        // load Ua tile
        for (int i = tid; i < H * KC; i += NTH) {
            int n = i / KC, k = i - n * KC;
            sU[n][k] = Ua[n * H + kb + k];
        }
        __syncthreads();

        #pragma unroll 8
        for (int kk = 0; kk < KC; ++kk) {
            float e[8], u[5];
            #pragma unroll
            for (int m = 0; m < 8; ++m) e[m] = sE[m0 + m][kk];   // warp-broadcast
            #pragma unroll
            for (int n = 0; n < 5; ++n) u[n] = sU[n0 + n][kk];   // stride-13 banks, conflict-free
            #pragma unroll
            for (int m = 0; m < 8; ++m)
                #pragma unroll
                for (int n = 0; n < 5; ++n) acc[m][n] += e[m] * u[n];
        }
    }

    // epilogue: tanh + Va-weighted reduce over this thread's 5 columns
    float part[8];
    #pragma unroll
    for (int m = 0; m < 8; ++m) part[m] = 0.f;
    #pragma unroll
    for (int n = 0; n < 5; ++n) {
        const float vq = sQ[n0 + n];
        const float vv = sV[n0 + n];
        #pragma unroll
        for (int m = 0; m < 8; ++m) part[m] += vv * tanhf(vq + acc[m][n]);
    }
    #pragma unroll
    for (int m = 0; m < 8; ++m) atomicAdd(&sS[m0 + m], part[m]);
    __syncthreads();
    for (int i = tid; i < TM; i += NTH) g_scores[b * T + t0 + i] = sS[i];
}

// ============================================================
// Kernel 3: softmax over T + context = attn @ enc
// grid = B, block = 256
// ============================================================
__global__ void k_ctx(const float* __restrict__ enc) {
    __shared__ float sW[T];
    __shared__ float red[256];
    const int b = blockIdx.x, tid = threadIdx.x;

    float m = -1e30f;
    for (int t = tid; t < T; t += 256) { float s = g_scores[b * T + t]; sW[t] = s; m = fmaxf(m, s); }
    red[tid] = m; __syncthreads();
    for (int s = 128; s > 0; s >>= 1) { if (tid < s) red[tid] = fmaxf(red[tid], red[tid + s]); __syncthreads(); }
    m = red[0];
    __syncthreads();

    float sum = 0.f;
    for (int t = tid; t < T; t += 256) { float e = __expf(sW[t] - m); sW[t] = e; sum += e; }
    red[tid] = sum; __syncthreads();
    for (int s = 128; s > 0; s >>= 1) { if (tid < s) red[tid] += red[tid + s]; __syncthreads(); }
    const float inv = 1.0f / red[0];
    __syncthreads();

    if (tid < H) {
        const float* eB = enc + (long)b * T * H + tid;   // column tid, coalesced across threads
        float c0 = 0.f, c1 = 0.f, c2 = 0.f, c3 = 0.f;
        #pragma unroll 2
        for (int t = 0; t < T; t += 4) {
            c0 += sW[t + 0] * eB[(t + 0) * H];
            c1 += sW[t + 1] * eB[(t + 1) * H];
            c2 += sW[t + 2] * eB[(t + 2) * H];
            c3 += sW[t + 3] * eB[(t + 3) * H];
        }
        g_context[b * H + tid] = (c0 + c1 + c2 + c3) * inv;
    }
}

// ============================================================
// Kernel 4: decoder — gates_base once, then 5 cheap recurrent steps
// grid = B, block = 256
// ============================================================
__global__ void k_dec(const float* __restrict__ x, const float* __restrict__ c0in,
                      const float* __restrict__ Wih, const float* __restrict__ bih,
                      const float* __restrict__ W1, const float* __restrict__ b1,
                      const float* __restrict__ W2, const float* __restrict__ b2,
                      const float* __restrict__ W3, const float* __restrict__ b3,
                      float* __restrict__ out) {
    __shared__ float sCtx[H];
    __shared__ float sGB[G4];
    __shared__ float sR[H];
    __shared__ float sO1[100];
    __shared__ float sO2[50];
    __shared__ float sRed[64];
    __shared__ float sY;

    const int b = blockIdx.x, tid = threadIdx.x;
    for (int i = tid; i < H; i += 256) sCtx[i] = g_context[b * H + i];
    __syncthreads();

    // gates_base = context @ W_ih[:,1:].T + b_ih + h_pre
    for (int g = tid; g < G4; g += 256) {
        const float* w = Wih + g * (H + 1);     // row: [x-weight, 200 context weights]
        float a0 = bih[g] + g_hpre[b * G4 + g], a1 = 0.f;
        #pragma unroll 4
        for (int k = 0; k < H; k += 2) { a0 += w[1 + k] * sCtx[k]; a1 += w[2 + k] * sCtx[k + 1]; }
        sGB[g] = a0 + a1;
    }
    __syncthreads();

    float xt = x[b];
    for (int s = 0; s < NSTEP; ++s) {
        if (tid < H) {
            const int n = tid;
            const float gi = sGB[n]           + xt * Wih[(n)           * (H + 1)];
            const float gf = sGB[H + n]       + xt * Wih[(H + n)       * (H + 1)];
            const float gg = sGB[2 * H + n]   + xt * Wih[(2 * H + n)   * (H + 1)];
            const float go = sGB[3 * H + n]   + xt * Wih[(3 * H + n)   * (H + 1)];
            const float c  = sigm(gf) * c0in[b * H + n] + sigm(gi) * tanhf(gg);
            const float h  = sigm(go) * tanhf(c);
            sR[n] = fmaxf(h, 0.f);
        }
        __syncthreads();
        if (tid < 100) {
            const float* w = W1 + tid * H;
            float a0 = b1[tid], a1 = 0.f;
            #pragma unroll 4
            for (int k = 0; k < H; k += 2) { a0 += w[k] * sR[k]; a1 += w[k + 1] * sR[k + 1]; }
            sO1[tid] = fmaxf(a0 + a1, 0.f);
        }
        __syncthreads();
        if (tid < 50) {
            const float* w = W2 + tid * 100;
            float a0 = b2[tid], a1 = 0.f;
            #pragma unroll 4
            for (int k = 0; k < 100; k += 2) { a0 += w[k] * sO1[k]; a1 += w[k + 1] * sO1[k + 1]; }
            sO2[tid] = fmaxf(a0 + a1, 0.f);
        }
        __syncthreads();
        if (tid < 50) sRed[tid] = W3[tid] * sO2[tid];
        __syncthreads();
        if (tid == 0) {
            float y = b3[0];
            for (int k = 0; k < 50; ++k) y += sRed[k];
            out[b * NSTEP + s] = y;
            sY = y;
        }
        __syncthreads();
        xt = sY;           // decoded output feeds back as next input
    }
}

// ============================================================
extern "C" void kernel_launch(void* const* d_in, const int* in_sizes, int n_in,
                              void* d_out, int out_size) {
    const float* x   = (const float*)d_in[0];
    const float* h0  = (const float*)d_in[1];
    const float* c0  = (const float*)d_in[2];
    const float* enc = (const float*)d_in[3];
    const float* Wa  = (const float*)d_in[4];
    const float* ba  = (const float*)d_in[5];
    const float* Ua  = (const float*)d_in[6];
    const float* bua = (const float*)d_in[7];
    const float* Va  = (const float*)d_in[8];
    // d_in[9] = bva : softmax-shift-invariant, unused
    const float* Wih = (const float*)d_in[10];
    // d_in[11] = W_hh (folded into h_pre)
    const float* Whh = (const float*)d_in[11];
    const float* bih = (const float*)d_in[12];
    const float* bhh = (const float*)d_in[13];
    const float* W1  = (const float*)d_in[14];
    const float* b1  = (const float*)d_in[15];
    const float* W2  = (const float*)d_in[16];
    const float* b2  = (const float*)d_in[17];
    const float* W3  = (const float*)d_in[18];
    const float* b3  = (const float*)d_in[19];
    float* out = (float*)d_out;

    k_pre<<<B, 256>>>(h0, Wa, ba, Whh, bhh);
    k_scores<<<dim3(T / TM, B), NTH>>>(enc, Ua, bua, Va);
    k_ctx<<<B, 256>>>(enc);
    k_dec<<<B, 256>>>(x, c0, Wih, bih, W1, b1, W2, b2, W3, b3, out);
}